// round 12
// baseline (speedup 1.0000x reference)
#include <cuda_runtime.h>
#include <cuda_bf16.h>
#include <cuda_fp16.h>
#include <cuda_fp8.h>
#include <cstdint>

// Problem constants
#define VOCAB  128
#define EDIM   64
#define HDIM   256
#define TLEN   128
#define BATCH  8192
#define NOUT   16384   // VOCAB * TLEN
#define STEPS  15

// true spike limit is 1/(1-0.7^15) ~= 1.00477; use 0.9 for cross-numerics slack
#define LIM_SAFE 0.9f
#define P_SCALE    128.0f
#define P_INVSCALE (1.0f / 128.0f)

// ---------------- scratch (static device globals; no allocation) -------------
__device__ __align__(16) unsigned char g_P[TLEN * VOCAB * HDIM];  // 4 MB fp8 P[t,v,h]*128
__device__ float         g_x[BATCH * HDIM];              // 8 MB: input projection
__device__ float         g_thresh2;                      // (min_j (LIM-b0[j])/||W0[j]||)^2
__device__ int           g_bias_ok;                      // biases below limit & thresh>0
__device__ int           g_notsafe;                      // 1 = some row violates cert

// fp8x2 (16 bits) -> half2
__device__ __forceinline__ __half2 fp8x2_to_half2(unsigned short v) {
    unsigned r;
    asm("cvt.rn.f16x2.e4m3x2 %0, %1;" : "=r"(r) : "h"(v));
    return *(__half2*)&r;
}

// ---------------- k_mega1: ONE-WAVE persistent buildP + wnorm + fill ---------
// Grid = 296 = 2 blocks/SM exactly (enforced by __launch_bounds__(256,2)):
//   blocks [0,128):   buildP workers, 2 (t,vbase) tiles each (256 tiles total)
//   block  128:       wnorm (certificate threshold precompute)
//   blocks [129,296): fill, grid-stride over 1024 (nbase x btile) units
// All roles are resident from cycle 0 -> fill writes at the DRAM roofline for
// the whole kernel while buildP's FMA work rides the compute pipes beside it.
#define BP_BLKS   128
#define WN_BLK    128
#define NBLOCKS   296
#define FB        (NBLOCKS - BP_BLKS - 1)   // 167 fill blocks
#define OROWS     32
#define NUNITS    (4 * (BATCH / OROWS))     // 1024 fill units
__global__ void __launch_bounds__(256, 2) k_mega1(const float* __restrict__ emb,
                                                  const float* __restrict__ in_W,
                                                  const float* __restrict__ lif_W,
                                                  const float* __restrict__ lif_b,
                                                  const float* __restrict__ out_b,
                                                  float*       __restrict__ out) {
    __shared__ __align__(16) char sm[16 * 1024 + 2 * 1024 + 32];
    const int bx = blockIdx.x;
    const int j  = threadIdx.x;

    if (bx < BP_BLKS) {
        // ---------------- buildP role (2 tiles per block) ----------------
        // P[t,v,h] = dot(emb[v,:], in_W[h, t*64 : t*64+64]) stored fp8*128.
        float* emb_s = (float*)sm;                       // 16 KB: 64 vocab rows
        uint4* st4   = (uint4*)(sm + 16 * 1024);         // 2 KB fp8 staging
        for (int tile = 2 * bx; tile < 2 * bx + 2; tile++) {
            const int t     = tile >> 1;
            const int vbase = (tile & 1) * 64;
            __syncthreads();  // protect emb_s reuse across tiles
            for (int i = j; i < 64 * EDIM; i += 256) emb_s[i] = emb[vbase * EDIM + i];
            float4 w4[16];
            const float4* src = (const float4*)(in_W + (size_t)j * 8192 + t * 64);
#pragma unroll
            for (int q = 0; q < 16; q++) w4[q] = src[q];
            __syncthreads();

            unsigned char* st = (unsigned char*)st4;
            for (int vg = 0; vg < 64; vg += 8) {
#pragma unroll
                for (int v2 = 0; v2 < 8; v2++) {
                    const float4* ev4 = (const float4*)(emb_s + (vg + v2) * EDIM);
                    float p = 0.f;
#pragma unroll
                    for (int q = 0; q < 16; q++) {
                        const float4 e = ev4[q];
                        p += e.x * w4[q].x + e.y * w4[q].y + e.z * w4[q].z + e.w * w4[q].w;
                    }
                    st[v2 * HDIM + j] = __nv_cvt_float_to_fp8(p * P_SCALE, __NV_SATFINITE, __NV_E4M3);
                }
                __syncthreads();
                if (j < 128)
                    ((uint4*)(g_P + (size_t)((t << 7) + vbase + vg) * HDIM))[j] = st4[j];
                __syncthreads();
            }
        }
        return;
    }

    if (bx == WN_BLK) {
        // ---------------- wnorm role ----------------
        // no-spike cert: for all b, ||x_b|| < min_j (LIM_SAFE - b0[j]) / ||W0[j]||
        // (Cauchy-Schwarz on base = x @ W0^T + b0), plus layer-1 bias < LIM_SAFE.
        float* red   = (float*)sm;
        int*   okred = (int*)(sm + 1024);
        if (j == 0) { *okred = 1; g_notsafe = 0; }
        __syncthreads();
        float w2 = 0.f;
        const float4* row = (const float4*)(lif_W + (size_t)j * HDIM);
#pragma unroll
        for (int q = 0; q < 64; q++) {
            const float4 wv = row[q];
            w2 += wv.x * wv.x + wv.y * wv.y + wv.z * wv.z + wv.w * wv.w;
        }
        const float margin = LIM_SAFE - lif_b[j];
        float th = margin * rsqrtf(fmaxf(w2, 1e-30f));
        if (margin <= 0.f || lif_b[HDIM + j] >= LIM_SAFE) atomicAnd(okred, 0);
        red[j] = th;
        __syncthreads();
        for (int o = 128; o > 0; o >>= 1) {
            if (j < o) red[j] = fminf(red[j], red[j + o]);
            __syncthreads();
        }
        if (j == 0) {
            g_bias_ok = *okred;
            const float t = fmaxf(red[0], 0.f);
            g_thresh2 = t * t;
        }
        return;
    }

    // ---------------- fill role (persistent grid-stride) ----------------
    const int fb = bx - (BP_BLKS + 1);
    for (int u = fb; u < NUNITS; u += FB) {
        const int nbase = (u & 3) * 4096;
        const int b0    = (u >> 2) * OROWS;
        float4 bias[4];
#pragma unroll
        for (int v = 0; v < 4; v++)
            bias[v] = *(const float4*)(out_b + nbase + (v * 256 + j) * 4);
#pragma unroll 4
        for (int r = 0; r < OROWS; r++) {
            float* dst = out + (size_t)(b0 + r) * NOUT + nbase;
#pragma unroll
            for (int v = 0; v < 4; v++)
                __stcs((float4*)(dst + (v * 256 + j) * 4), bias[v]);
        }
    }
}

// ---------------- x[b,:] = in_b + (1/128) * sum_t P8[t, ids[b,t], :] ---------
// Runs serially after k_mega1 on an idle memory system: pure L2-read-bound
// (268 MB logical reads of the 4 MB P table, at the LTS roofline).
__global__ void __launch_bounds__(256) k_gather(const int* __restrict__ ids,
                                                const float* __restrict__ in_b) {
    __shared__ int ids_s[8][TLEN];
    const int lane = threadIdx.x & 31;
    const int w    = threadIdx.x >> 5;
    const int b    = blockIdx.x * 8 + w;

    for (int i = lane; i < TLEN; i += 32) ids_s[w][i] = ids[b * TLEN + i];
    __syncwarp();

    __half2 a0 = __float2half2_rn(0.f);
    __half2 a1 = a0, a2 = a0, a3 = a0;

    const ushort4* Pb = (const ushort4*)g_P;  // 32 ushort4 per (t,v) row
#pragma unroll 4
    for (int t = 0; t < TLEN; t++) {
        const int id = ids_s[w][t];
        const ushort4 p = Pb[(size_t)((t << 7) + id) * 32 + lane];
        a0 = __hadd2(a0, fp8x2_to_half2(p.x));
        a1 = __hadd2(a1, fp8x2_to_half2(p.y));
        a2 = __hadd2(a2, fp8x2_to_half2(p.z));
        a3 = __hadd2(a3, fp8x2_to_half2(p.w));
    }

    float v[8];
    {
        float2 f0 = __half22float2(a0);
        float2 f1 = __half22float2(a1);
        float2 f2 = __half22float2(a2);
        float2 f3 = __half22float2(a3);
        v[0] = f0.x; v[1] = f0.y; v[2] = f1.x; v[3] = f1.y;
        v[4] = f2.x; v[5] = f2.y; v[6] = f3.x; v[7] = f3.y;
    }
    const float4 b0 = *(const float4*)(in_b + lane * 8);
    const float4 b1 = *(const float4*)(in_b + lane * 8 + 4);
    v[0] = v[0] * P_INVSCALE + b0.x; v[1] = v[1] * P_INVSCALE + b0.y;
    v[2] = v[2] * P_INVSCALE + b0.z; v[3] = v[3] * P_INVSCALE + b0.w;
    v[4] = v[4] * P_INVSCALE + b1.x; v[5] = v[5] * P_INVSCALE + b1.y;
    v[6] = v[6] * P_INVSCALE + b1.z; v[7] = v[7] * P_INVSCALE + b1.w;

    float* dst = g_x + (size_t)b * HDIM + lane * 8;
    __stcs((float4*)(dst + 0), make_float4(v[0], v[1], v[2], v[3]));
    __stcs((float4*)(dst + 4), make_float4(v[4], v[5], v[6], v[7]));

    float ns = 0.f;
#pragma unroll
    for (int i = 0; i < 8; i++) ns += v[i] * v[i];
#pragma unroll
    for (int o = 16; o > 0; o >>= 1) ns += __shfl_xor_sync(0xffffffffu, ns, o);
    if (lane == 0 && ns >= g_thresh2) g_notsafe = 1;
}

// ---------------- k_post: fused LIF fallback + output correction -------------
// Grid-strided with a small grid so the (always-taken) early exit costs ~1 us.
// Fallback: exact 15-step LIF for 16 rows/group, then add out_W columns.
#define ROWS 16
#define POSTBLK 128
__global__ void __launch_bounds__(256) k_post(const float* __restrict__ lif_W,
                                              const float* __restrict__ rec_W,
                                              const float* __restrict__ lif_b,
                                              const float* __restrict__ out_W,
                                              float*       __restrict__ out) {
    if (g_bias_ok && !g_notsafe) return;  // certificate holds: no spikes

    __shared__ float    x_s[ROWS * HDIM];     // 16 KB
    __shared__ unsigned s0b[ROWS][8];
    __shared__ unsigned s1b[ROWS][8];
    __shared__ unsigned u0[8], u1[8];
    __shared__ int any0s, any1s;

    const int j    = threadIdx.x;
    const int lane = j & 31;
    const int wi   = j >> 5;

    const float bj0 = lif_b[j];
    const float bj1 = lif_b[HDIM + j];
    const float* LW1 = lif_W + (size_t)HDIM * HDIM + (size_t)j * HDIM;
    const float* RW0 = rec_W + (size_t)j * HDIM;
    const float* RW1 = rec_W + (size_t)HDIM * HDIM + (size_t)j * HDIM;
    const float4* w0row = (const float4*)(lif_W + (size_t)j * HDIM);

    for (int grp = blockIdx.x; grp < BATCH / ROWS; grp += POSTBLK) {
        const int b0 = grp * ROWS;

        for (int i = j; i < ROWS * HDIM; i += 256) x_s[i] = g_x[b0 * HDIM + i];
        if (j < ROWS * 8) { s0b[j >> 3][j & 7] = 0u; s1b[j >> 3][j & 7] = 0u; }
        if (j < 8) { u0[j] = 0u; u1[j] = 0u; }
        if (j == 0) { any0s = 0; any1s = 0; }
        __syncthreads();

        // base[r] = x[r,:] @ lif_W0[j,:] + lif_b0[j]  (step-invariant)
        float base[ROWS];
#pragma unroll
        for (int r = 0; r < ROWS; r++) base[r] = 0.f;
        for (int k = 0; k < HDIM; k += 4) {
            const float4 wv = w0row[k >> 2];
#pragma unroll
            for (int r = 0; r < ROWS; r++) {
                const float4 xv = *(const float4*)&x_s[r * HDIM + k];
                base[r] += xv.x * wv.x + xv.y * wv.y + xv.z * wv.z + xv.w * wv.w;
            }
        }
#pragma unroll
        for (int r = 0; r < ROWS; r++) base[r] += bj0;

        float v0[ROWS], v1[ROWS];
#pragma unroll
        for (int r = 0; r < ROWS; r++) { v0[r] = 0.f; v1[r] = 0.f; }

        for (int step = 0; step < STEPS; step++) {
            // ======== layer 0 ========
            float cur[ROWS];
#pragma unroll
            for (int r = 0; r < ROWS; r++) cur[r] = base[r];
            if (any0s) {
                for (int k = 0; k < HDIM; k++) {
                    const unsigned bit = 1u << (k & 31);
                    const int wk = k >> 5;
                    if (u0[wk] & bit) {
                        float wv = RW0[k];
#pragma unroll
                        for (int r = 0; r < ROWS; r++)
                            if (s0b[r][wk] & bit) cur[r] += wv;
                    }
                }
            }
            unsigned spmask = 0u;
#pragma unroll
            for (int r = 0; r < ROWS; r++) {
                v0[r] = 0.7f * v0[r] + 0.3f * cur[r];
                if (v0[r] >= 1.0f) { spmask |= (1u << r); v0[r] = 0.f; }
            }
            __syncthreads();
#pragma unroll
            for (int r = 0; r < ROWS; r++) {
                unsigned bal = __ballot_sync(0xffffffffu, (spmask >> r) & 1u);
                if (lane == 0) s0b[r][wi] = bal;
            }
            __syncthreads();
            if (j < 8) {
                unsigned o = 0;
#pragma unroll
                for (int r = 0; r < ROWS; r++) o |= s0b[r][j];
                u0[j] = o;
            }
            __syncthreads();
            if (j == 0)
                any0s = (u0[0] | u0[1] | u0[2] | u0[3] | u0[4] | u0[5] | u0[6] | u0[7]) ? 1 : 0;
            __syncthreads();

            // ======== layer 1 (input = NEW layer-0 spikes) ========
#pragma unroll
            for (int r = 0; r < ROWS; r++) cur[r] = bj1;
            if (any0s) {
                for (int k = 0; k < HDIM; k++) {
                    const unsigned bit = 1u << (k & 31);
                    const int wk = k >> 5;
                    if (u0[wk] & bit) {
                        float wv = LW1[k];
#pragma unroll
                        for (int r = 0; r < ROWS; r++)
                            if (s0b[r][wk] & bit) cur[r] += wv;
                    }
                }
            }
            if (any1s) {
                for (int k = 0; k < HDIM; k++) {
                    const unsigned bit = 1u << (k & 31);
                    const int wk = k >> 5;
                    if (u1[wk] & bit) {
                        float wv = RW1[k];
#pragma unroll
                        for (int r = 0; r < ROWS; r++)
                            if (s1b[r][wk] & bit) cur[r] += wv;
                    }
                }
            }
            spmask = 0u;
#pragma unroll
            for (int r = 0; r < ROWS; r++) {
                v1[r] = 0.7f * v1[r] + 0.3f * cur[r];
                if (v1[r] >= 1.0f) { spmask |= (1u << r); v1[r] = 0.f; }
            }
            __syncthreads();
#pragma unroll
            for (int r = 0; r < ROWS; r++) {
                unsigned bal = __ballot_sync(0xffffffffu, (spmask >> r) & 1u);
                if (lane == 0) s1b[r][wi] = bal;
            }
            __syncthreads();
            if (j < 8) {
                unsigned o = 0;
#pragma unroll
                for (int r = 0; r < ROWS; r++) o |= s1b[r][j];
                u1[j] = o;
            }
            __syncthreads();
            if (j == 0)
                any1s = (u1[0] | u1[1] | u1[2] | u1[3] | u1[4] | u1[5] | u1[6] | u1[7]) ? 1 : 0;
            __syncthreads();
        }

        // ---- apply corrections: out[b,:] += sum_{k fired} out_W[:,k] ----
        for (int r = 0; r < ROWS; r++) {
            unsigned any = 0;
#pragma unroll
            for (int w8 = 0; w8 < 8; w8++) any |= s1b[r][w8];
            if (!any) continue;
            float* dst = out + (size_t)(b0 + r) * NOUT;
#pragma unroll
            for (int w8 = 0; w8 < 8; w8++) {
                unsigned m = s1b[r][w8];
                while (m) {
                    int k = (w8 << 5) + __ffs(m) - 1;
                    m &= m - 1;
                    for (int c = j; c < NOUT; c += 256)
                        dst[c] += out_W[(size_t)c * HDIM + k];
                }
            }
        }
        __syncthreads();  // smem reuse across grid-stride groups
    }
}

// ---------------- launch ------------------------------------------------------
extern "C" void kernel_launch(void* const* d_in, const int* in_sizes, int n_in,
                              void* d_out, int out_size) {
    const int*   ids   = (const int*)d_in[0];
    const float* emb   = (const float*)d_in[1];
    const float* in_W  = (const float*)d_in[2];
    const float* in_b  = (const float*)d_in[3];
    const float* lif_W = (const float*)d_in[4];
    const float* lif_b = (const float*)d_in[5];
    const float* rec_W = (const float*)d_in[6];
    const float* out_W = (const float*)d_in[7];
    const float* out_b = (const float*)d_in[8];
    float* out = (float*)d_out;

    k_mega1<<<NBLOCKS, 256>>>(emb, in_W, lif_W, lif_b, out_b, out);
    k_gather<<<BATCH / 8, 256>>>(ids, in_b);
    k_post<<<POSTBLK, 256>>>(lif_W, rec_W, lif_b, out_W, out);
}

// round 13
// speedup vs baseline: 1.3352x; 1.3352x over previous
#include <cuda_runtime.h>
#include <cuda_bf16.h>
#include <cuda_fp16.h>
#include <cuda_fp8.h>
#include <cstdint>

// Problem constants
#define VOCAB  128
#define EDIM   64
#define HDIM   256
#define TLEN   128
#define BATCH  8192
#define NOUT   16384   // VOCAB * TLEN
#define STEPS  15

// true spike limit is 1/(1-0.7^15) ~= 1.00477; use 0.9 for cross-numerics slack
#define LIM_SAFE 0.9f
#define P_SCALE    128.0f
#define P_INVSCALE (1.0f / 128.0f)

// ---------------- scratch (static device globals; no allocation) -------------
__device__ __align__(16) unsigned char g_P[TLEN * VOCAB * HDIM];  // 4 MB fp8 P[t,v,h]*128
__device__ float         g_x[BATCH * HDIM];              // 8 MB: input projection
__device__ float         g_thresh2;                      // (min_j (LIM-b0[j])/||W0[j]||)^2
__device__ int           g_bias_ok;                      // biases below limit & thresh>0
__device__ int           g_notsafe;                      // 1 = some row violates cert

// fp8x2 (16 bits) -> half2
__device__ __forceinline__ __half2 fp8x2_to_half2(unsigned short v) {
    unsigned r;
    asm("cvt.rn.f16x2.e4m3x2 %0, %1;" : "=r"(r) : "h"(v));
    return *(__half2*)&r;
}

// ---------------- k_mega1: INTERLEAVED buildP + wnorm + fill -----------------
// Grid = 769. Role by block index:
//   bx < 768 && bx % 3 == 2 : buildP tile bx/3        (256 blocks)
//   bx == 768               : wnorm                    (1 block)
//   otherwise               : fill, fb = bx - (bx+1)/3 (512 blocks, 2 units each)
// Interleaving puts ~2 fill : 1 buildP in every dispatch wave, so the 536 MB
// write stream runs at the DRAM roofline from cycle 0 while buildP's ~12 us of
// FMA work hides inside it. Fill blocks are short -> retire-and-replace keeps
// all SMs saturated (the failure mode of the persistent variant).
#define OROWS     32
#define NUNITS    (4 * (BATCH / OROWS))     // 1024 fill units
#define NBLOCKS   769
__global__ void __launch_bounds__(256) k_mega1(const float* __restrict__ emb,
                                               const float* __restrict__ in_W,
                                               const float* __restrict__ lif_W,
                                               const float* __restrict__ lif_b,
                                               const float* __restrict__ out_b,
                                               float*       __restrict__ out) {
    __shared__ __align__(16) char sm[16 * 1024 + 2 * 1024 + 32];
    const int bx = blockIdx.x;
    const int j  = threadIdx.x;

    if (bx < 768 && (bx % 3) == 2) {
        // ---------------- buildP role (tile = bx/3) ----------------
        // P[t,v,h] = dot(emb[v,:], in_W[h, t*64 : t*64+64]) stored fp8*128.
        float* emb_s = (float*)sm;                       // 16 KB: 64 vocab rows
        uint4* st4   = (uint4*)(sm + 16 * 1024);         // 2 KB fp8 staging
        const int tile  = bx / 3;
        const int t     = tile >> 1;
        const int vbase = (tile & 1) * 64;
        for (int i = j; i < 64 * EDIM; i += 256) emb_s[i] = emb[vbase * EDIM + i];
        float4 w4[16];
        const float4* src = (const float4*)(in_W + (size_t)j * 8192 + t * 64);
#pragma unroll
        for (int q = 0; q < 16; q++) w4[q] = src[q];
        __syncthreads();

        unsigned char* st = (unsigned char*)st4;
        for (int vg = 0; vg < 64; vg += 8) {
#pragma unroll
            for (int v2 = 0; v2 < 8; v2++) {
                const float4* ev4 = (const float4*)(emb_s + (vg + v2) * EDIM);
                float p = 0.f;
#pragma unroll
                for (int q = 0; q < 16; q++) {
                    const float4 e = ev4[q];
                    p += e.x * w4[q].x + e.y * w4[q].y + e.z * w4[q].z + e.w * w4[q].w;
                }
                st[v2 * HDIM + j] = __nv_cvt_float_to_fp8(p * P_SCALE, __NV_SATFINITE, __NV_E4M3);
            }
            __syncthreads();
            if (j < 128)
                ((uint4*)(g_P + (size_t)((t << 7) + vbase + vg) * HDIM))[j] = st4[j];
            __syncthreads();
        }
        return;
    }

    if (bx == 768) {
        // ---------------- wnorm role ----------------
        // no-spike cert: for all b, ||x_b|| < min_j (LIM_SAFE - b0[j]) / ||W0[j]||
        // (Cauchy-Schwarz on base = x @ W0^T + b0), plus layer-1 bias < LIM_SAFE.
        float* red   = (float*)sm;
        int*   okred = (int*)(sm + 1024);
        if (j == 0) { *okred = 1; g_notsafe = 0; }
        __syncthreads();
        float w2 = 0.f;
        const float4* row = (const float4*)(lif_W + (size_t)j * HDIM);
#pragma unroll
        for (int q = 0; q < 64; q++) {
            const float4 wv = row[q];
            w2 += wv.x * wv.x + wv.y * wv.y + wv.z * wv.z + wv.w * wv.w;
        }
        const float margin = LIM_SAFE - lif_b[j];
        float th = margin * rsqrtf(fmaxf(w2, 1e-30f));
        if (margin <= 0.f || lif_b[HDIM + j] >= LIM_SAFE) atomicAnd(okred, 0);
        red[j] = th;
        __syncthreads();
        for (int o = 128; o > 0; o >>= 1) {
            if (j < o) red[j] = fminf(red[j], red[j + o]);
            __syncthreads();
        }
        if (j == 0) {
            g_bias_ok = *okred;
            const float t = fmaxf(red[0], 0.f);
            g_thresh2 = t * t;
        }
        return;
    }

    // ---------------- fill role ----------------
    // fb in [0,512). Units fb and fb+512 share (fb & 3) -> same nbase, so the
    // bias registers are loaded once.
    const int fb = bx - (bx + 1) / 3;
    const int nbase = (fb & 3) * 4096;
    float4 bias[4];
#pragma unroll
    for (int v = 0; v < 4; v++)
        bias[v] = *(const float4*)(out_b + nbase + (v * 256 + j) * 4);

#pragma unroll
    for (int half = 0; half < 2; half++) {
        const int u  = fb + half * 512;
        const int b0 = (u >> 2) * OROWS;
#pragma unroll 4
        for (int r = 0; r < OROWS; r++) {
            float* dst = out + (size_t)(b0 + r) * NOUT + nbase;
#pragma unroll
            for (int v = 0; v < 4; v++)
                __stcs((float4*)(dst + (v * 256 + j) * 4), bias[v]);
        }
    }
}

// ---------------- x[b,:] = in_b + (1/128) * sum_t P8[t, ids[b,t], :] ---------
// Runs serially after k_mega1 on an idle memory system: pure L2-read-bound
// (268 MB logical reads of the 4 MB P table, at the LTS roofline).
__global__ void __launch_bounds__(256) k_gather(const int* __restrict__ ids,
                                                const float* __restrict__ in_b) {
    __shared__ int ids_s[8][TLEN];
    const int lane = threadIdx.x & 31;
    const int w    = threadIdx.x >> 5;
    const int b    = blockIdx.x * 8 + w;

    for (int i = lane; i < TLEN; i += 32) ids_s[w][i] = ids[b * TLEN + i];
    __syncwarp();

    __half2 a0 = __float2half2_rn(0.f);
    __half2 a1 = a0, a2 = a0, a3 = a0;

    const ushort4* Pb = (const ushort4*)g_P;  // 32 ushort4 per (t,v) row
#pragma unroll 4
    for (int t = 0; t < TLEN; t++) {
        const int id = ids_s[w][t];
        const ushort4 p = Pb[(size_t)((t << 7) + id) * 32 + lane];
        a0 = __hadd2(a0, fp8x2_to_half2(p.x));
        a1 = __hadd2(a1, fp8x2_to_half2(p.y));
        a2 = __hadd2(a2, fp8x2_to_half2(p.z));
        a3 = __hadd2(a3, fp8x2_to_half2(p.w));
    }

    float v[8];
    {
        float2 f0 = __half22float2(a0);
        float2 f1 = __half22float2(a1);
        float2 f2 = __half22float2(a2);
        float2 f3 = __half22float2(a3);
        v[0] = f0.x; v[1] = f0.y; v[2] = f1.x; v[3] = f1.y;
        v[4] = f2.x; v[5] = f2.y; v[6] = f3.x; v[7] = f3.y;
    }
    const float4 b0 = *(const float4*)(in_b + lane * 8);
    const float4 b1 = *(const float4*)(in_b + lane * 8 + 4);
    v[0] = v[0] * P_INVSCALE + b0.x; v[1] = v[1] * P_INVSCALE + b0.y;
    v[2] = v[2] * P_INVSCALE + b0.z; v[3] = v[3] * P_INVSCALE + b0.w;
    v[4] = v[4] * P_INVSCALE + b1.x; v[5] = v[5] * P_INVSCALE + b1.y;
    v[6] = v[6] * P_INVSCALE + b1.z; v[7] = v[7] * P_INVSCALE + b1.w;

    float* dst = g_x + (size_t)b * HDIM + lane * 8;
    __stcs((float4*)(dst + 0), make_float4(v[0], v[1], v[2], v[3]));
    __stcs((float4*)(dst + 4), make_float4(v[4], v[5], v[6], v[7]));

    float ns = 0.f;
#pragma unroll
    for (int i = 0; i < 8; i++) ns += v[i] * v[i];
#pragma unroll
    for (int o = 16; o > 0; o >>= 1) ns += __shfl_xor_sync(0xffffffffu, ns, o);
    if (lane == 0 && ns >= g_thresh2) g_notsafe = 1;
}

// ---------------- k_post: fused LIF fallback + output correction -------------
// Grid-strided with a small grid so the (always-taken) early exit costs ~1 us.
// Fallback: exact 15-step LIF for 16 rows/group, then add out_W columns.
#define ROWS 16
#define POSTBLK 128
__global__ void __launch_bounds__(256) k_post(const float* __restrict__ lif_W,
                                              const float* __restrict__ rec_W,
                                              const float* __restrict__ lif_b,
                                              const float* __restrict__ out_W,
                                              float*       __restrict__ out) {
    if (g_bias_ok && !g_notsafe) return;  // certificate holds: no spikes

    __shared__ float    x_s[ROWS * HDIM];     // 16 KB
    __shared__ unsigned s0b[ROWS][8];
    __shared__ unsigned s1b[ROWS][8];
    __shared__ unsigned u0[8], u1[8];
    __shared__ int any0s, any1s;

    const int j    = threadIdx.x;
    const int lane = j & 31;
    const int wi   = j >> 5;

    const float bj0 = lif_b[j];
    const float bj1 = lif_b[HDIM + j];
    const float* LW1 = lif_W + (size_t)HDIM * HDIM + (size_t)j * HDIM;
    const float* RW0 = rec_W + (size_t)j * HDIM;
    const float* RW1 = rec_W + (size_t)HDIM * HDIM + (size_t)j * HDIM;
    const float4* w0row = (const float4*)(lif_W + (size_t)j * HDIM);

    for (int grp = blockIdx.x; grp < BATCH / ROWS; grp += POSTBLK) {
        const int b0 = grp * ROWS;

        for (int i = j; i < ROWS * HDIM; i += 256) x_s[i] = g_x[b0 * HDIM + i];
        if (j < ROWS * 8) { s0b[j >> 3][j & 7] = 0u; s1b[j >> 3][j & 7] = 0u; }
        if (j < 8) { u0[j] = 0u; u1[j] = 0u; }
        if (j == 0) { any0s = 0; any1s = 0; }
        __syncthreads();

        // base[r] = x[r,:] @ lif_W0[j,:] + lif_b0[j]  (step-invariant)
        float base[ROWS];
#pragma unroll
        for (int r = 0; r < ROWS; r++) base[r] = 0.f;
        for (int k = 0; k < HDIM; k += 4) {
            const float4 wv = w0row[k >> 2];
#pragma unroll
            for (int r = 0; r < ROWS; r++) {
                const float4 xv = *(const float4*)&x_s[r * HDIM + k];
                base[r] += xv.x * wv.x + xv.y * wv.y + xv.z * wv.z + xv.w * wv.w;
            }
        }
#pragma unroll
        for (int r = 0; r < ROWS; r++) base[r] += bj0;

        float v0[ROWS], v1[ROWS];
#pragma unroll
        for (int r = 0; r < ROWS; r++) { v0[r] = 0.f; v1[r] = 0.f; }

        for (int step = 0; step < STEPS; step++) {
            // ======== layer 0 ========
            float cur[ROWS];
#pragma unroll
            for (int r = 0; r < ROWS; r++) cur[r] = base[r];
            if (any0s) {
                for (int k = 0; k < HDIM; k++) {
                    const unsigned bit = 1u << (k & 31);
                    const int wk = k >> 5;
                    if (u0[wk] & bit) {
                        float wv = RW0[k];
#pragma unroll
                        for (int r = 0; r < ROWS; r++)
                            if (s0b[r][wk] & bit) cur[r] += wv;
                    }
                }
            }
            unsigned spmask = 0u;
#pragma unroll
            for (int r = 0; r < ROWS; r++) {
                v0[r] = 0.7f * v0[r] + 0.3f * cur[r];
                if (v0[r] >= 1.0f) { spmask |= (1u << r); v0[r] = 0.f; }
            }
            __syncthreads();
#pragma unroll
            for (int r = 0; r < ROWS; r++) {
                unsigned bal = __ballot_sync(0xffffffffu, (spmask >> r) & 1u);
                if (lane == 0) s0b[r][wi] = bal;
            }
            __syncthreads();
            if (j < 8) {
                unsigned o = 0;
#pragma unroll
                for (int r = 0; r < ROWS; r++) o |= s0b[r][j];
                u0[j] = o;
            }
            __syncthreads();
            if (j == 0)
                any0s = (u0[0] | u0[1] | u0[2] | u0[3] | u0[4] | u0[5] | u0[6] | u0[7]) ? 1 : 0;
            __syncthreads();

            // ======== layer 1 (input = NEW layer-0 spikes) ========
#pragma unroll
            for (int r = 0; r < ROWS; r++) cur[r] = bj1;
            if (any0s) {
                for (int k = 0; k < HDIM; k++) {
                    const unsigned bit = 1u << (k & 31);
                    const int wk = k >> 5;
                    if (u0[wk] & bit) {
                        float wv = LW1[k];
#pragma unroll
                        for (int r = 0; r < ROWS; r++)
                            if (s0b[r][wk] & bit) cur[r] += wv;
                    }
                }
            }
            if (any1s) {
                for (int k = 0; k < HDIM; k++) {
                    const unsigned bit = 1u << (k & 31);
                    const int wk = k >> 5;
                    if (u1[wk] & bit) {
                        float wv = RW1[k];
#pragma unroll
                        for (int r = 0; r < ROWS; r++)
                            if (s1b[r][wk] & bit) cur[r] += wv;
                    }
                }
            }
            spmask = 0u;
#pragma unroll
            for (int r = 0; r < ROWS; r++) {
                v1[r] = 0.7f * v1[r] + 0.3f * cur[r];
                if (v1[r] >= 1.0f) { spmask |= (1u << r); v1[r] = 0.f; }
            }
            __syncthreads();
#pragma unroll
            for (int r = 0; r < ROWS; r++) {
                unsigned bal = __ballot_sync(0xffffffffu, (spmask >> r) & 1u);
                if (lane == 0) s1b[r][wi] = bal;
            }
            __syncthreads();
            if (j < 8) {
                unsigned o = 0;
#pragma unroll
                for (int r = 0; r < ROWS; r++) o |= s1b[r][j];
                u1[j] = o;
            }
            __syncthreads();
            if (j == 0)
                any1s = (u1[0] | u1[1] | u1[2] | u1[3] | u1[4] | u1[5] | u1[6] | u1[7]) ? 1 : 0;
            __syncthreads();
        }

        // ---- apply corrections: out[b,:] += sum_{k fired} out_W[:,k] ----
        for (int r = 0; r < ROWS; r++) {
            unsigned any = 0;
#pragma unroll
            for (int w8 = 0; w8 < 8; w8++) any |= s1b[r][w8];
            if (!any) continue;
            float* dst = out + (size_t)(b0 + r) * NOUT;
#pragma unroll
            for (int w8 = 0; w8 < 8; w8++) {
                unsigned m = s1b[r][w8];
                while (m) {
                    int k = (w8 << 5) + __ffs(m) - 1;
                    m &= m - 1;
                    for (int c = j; c < NOUT; c += 256)
                        dst[c] += out_W[(size_t)c * HDIM + k];
                }
            }
        }
        __syncthreads();  // smem reuse across grid-stride groups
    }
}

// ---------------- launch ------------------------------------------------------
extern "C" void kernel_launch(void* const* d_in, const int* in_sizes, int n_in,
                              void* d_out, int out_size) {
    const int*   ids   = (const int*)d_in[0];
    const float* emb   = (const float*)d_in[1];
    const float* in_W  = (const float*)d_in[2];
    const float* in_b  = (const float*)d_in[3];
    const float* lif_W = (const float*)d_in[4];
    const float* lif_b = (const float*)d_in[5];
    const float* rec_W = (const float*)d_in[6];
    const float* out_W = (const float*)d_in[7];
    const float* out_b = (const float*)d_in[8];
    float* out = (float*)d_out;

    k_mega1<<<NBLOCKS, 256>>>(emb, in_W, lif_W, lif_b, out_b, out);
    k_gather<<<BATCH / 8, 256>>>(ids, in_b);
    k_post<<<POSTBLK, 256>>>(lif_W, rec_W, lif_b, out_W, out);
}